// round 10
// baseline (speedup 1.0000x reference)
#include <cuda_runtime.h>
#include <cuda_fp16.h>
#include <stdint.h>

// Problem dims (fixed by the dataset)
#define FDIM 16384   // n_features
#define DDIM 768     // d_model
#define NB   1024    // B*S
#define MCONN 262144 // n_connections

// -------- scratch (device globals; no allocation allowed) --------
__device__ __half g_udTh[(size_t)FDIM * DDIM]; // up_decoder^T fp16: [F, D] (~25 MB)
__device__ __half g_XTh[(size_t)FDIM * NB];    // up_facts^T fp16:   [F, NB] (~33 MB)
__device__ int2   g_packed[MCONN];             // {xt byte offset = j*2048, value bits}
__device__ int    g_rowstart[FDIM + 1];        // CSR offsets over sorted i

// ---------------------------------------------------------------
// Inline int64-vs-int32 detection on the i_indices buffer (values
// < 16384 => odd int32-words of an int64 array are all zero; for
// int32 data the probed words are sorted indices ~8192 != 0).
// ---------------------------------------------------------------
__device__ __forceinline__ int detect_is64(const int* raw) {
    int q = MCONN / 4;
    int nz = 0;
#pragma unroll
    for (int k = 0; k < 8; k++) nz |= raw[2 * (q + k) + 1];
    return nz ? 0 : 1;
}

__device__ __forceinline__ int idx_at(const void* p, int is64, int m) {
    return is64 ? (int)((const long long*)p)[m] : ((const int*)p)[m];
}

// ================================================================
// K1: fused prep = transpose_ud | csr_scatter | j -> packed offset
// ================================================================
#define K1_UD   12288   // (FDIM/32)*(DDIM/32) = 512*24
#define K1_CSR  (K1_UD + 1024)
#define K1_TOT  (K1_CSR + 1024)

__global__ __launch_bounds__(256) void k1_prep(const float* __restrict__ up_dec,
                                               const void* __restrict__ ii,
                                               const void* __restrict__ jj) {
    int b = blockIdx.x;
    if (b < K1_UD) {
        __shared__ float tile[32][33];
        int bx = b & 511;          // F tile
        int by = b >> 9;           // D tile
        int c0 = bx * 32, r0 = by * 32;
        int tx = threadIdx.x & 31, ty = threadIdx.x >> 5;   // (32, 8)
#pragma unroll
        for (int k = 0; k < 32; k += 8)
            tile[ty + k][tx] = __ldcs(&up_dec[(size_t)(r0 + ty + k) * FDIM + (c0 + tx)]);
        __syncthreads();
#pragma unroll
        for (int k = 0; k < 32; k += 8)
            g_udTh[(size_t)(c0 + ty + k) * DDIM + (r0 + tx)] = __float2half(tile[tx][ty + k]);
    } else if (b < K1_CSR) {
        int m = (b - K1_UD) * 256 + threadIdx.x;
        int is64 = detect_is64((const int*)ii);
        int cur = idx_at(ii, is64, m);
        int prev = (m == 0) ? -1 : idx_at(ii, is64, m - 1);
        for (int i = prev + 1; i <= cur; i++) g_rowstart[i] = m;
        if (m == MCONN - 1)
            for (int i = cur + 1; i <= FDIM; i++) g_rowstart[i] = MCONN;
    } else {
        int m = (b - K1_CSR) * 256 + threadIdx.x;
        int is64 = detect_is64((const int*)ii);
        g_packed[m].x = idx_at(jj, is64, m) << 11;   // j * NB * sizeof(half)
    }
}

// ================================================================
// K2a: up_facts [NB,F] -> g_XTh [F,NB] fp16 (streaming reads)
// ================================================================
__global__ __launch_bounds__(256) void k2_xt(const float* __restrict__ up_facts) {
    __shared__ float tile[32][33];
    int bx = blockIdx.x & 511;     // F tile
    int by = blockIdx.x >> 9;      // NB tile
    int c0 = bx * 32, r0 = by * 32;
    int tx = threadIdx.x & 31, ty = threadIdx.x >> 5;
#pragma unroll
    for (int k = 0; k < 32; k += 8)
        tile[ty + k][tx] = __ldcs(&up_facts[(size_t)(r0 + ty + k) * FDIM + (c0 + tx)]);
    __syncthreads();
#pragma unroll
    for (int k = 0; k < 32; k += 8)
        g_XTh[(size_t)(c0 + ty + k) * NB + (r0 + tx)] = __float2half(tile[tx][ty + k]);
}

// ================================================================
// K2b: values[m] = <down_encoder[i_m,:], udT[j_m,:]>.
// One warp per i-group; de row in registers; 2 connections in
// flight (6 independent LDG.128) with interleaved reductions.
// ================================================================
__device__ __forceinline__ float dot24(const float a[3][8], const uint4* u, int lane) {
    float sum = 0.f;
#pragma unroll
    for (int k = 0; k < 3; k++) {
        uint4 bb = u[lane + 32 * k];
        const __half2* h = (const __half2*)&bb;
#pragma unroll
        for (int t = 0; t < 4; t++) {
            float2 f = __half22float2(h[t]);
            sum += a[k][2 * t] * f.x + a[k][2 * t + 1] * f.y;
        }
    }
    return sum;
}

__global__ __launch_bounds__(256) void k2_values(const float* __restrict__ de) {
    int warp = blockIdx.x * 8 + (threadIdx.x >> 5);
    int lane = threadIdx.x & 31;
    int i = warp;
    int s = g_rowstart[i];
    int e = g_rowstart[i + 1];
    if (s == e) return;

    // Cache de[i,:] lane slice: elements 8*(2*lane+64k) .. +7, k<3
    float a[3][8];
    const float4* dev = (const float4*)(de + (size_t)i * DDIM);
#pragma unroll
    for (int k = 0; k < 3; k++) {
        float4 p = dev[2 * lane + 64 * k];
        float4 q = dev[2 * lane + 64 * k + 1];
        a[k][0] = p.x; a[k][1] = p.y; a[k][2] = p.z; a[k][3] = p.w;
        a[k][4] = q.x; a[k][5] = q.y; a[k][6] = q.z; a[k][7] = q.w;
    }

    int m = s;
    for (; m + 2 <= e; m += 2) {
        int off0 = g_packed[m].x;
        int off1 = g_packed[m + 1].x;
        const uint4* u0 = (const uint4*)((const char*)g_udTh + ((size_t)off0 * (DDIM / NB)));
        // off = j*2048 bytes in XT units; udT row stride = DDIM*2 = 1536 bytes.
        // Recover j = off >> 11, then byte offset j*1536 = (off>>11)*1536.
        int j0 = off0 >> 11, j1 = off1 >> 11;
        u0 = (const uint4*)(g_udTh + (size_t)j0 * DDIM);
        const uint4* u1 = (const uint4*)(g_udTh + (size_t)j1 * DDIM);
        float s0 = dot24(a, u0, lane);
        float s1 = dot24(a, u1, lane);
#pragma unroll
        for (int o = 16; o; o >>= 1) {
            s0 += __shfl_xor_sync(0xffffffffu, s0, o);
            s1 += __shfl_xor_sync(0xffffffffu, s1, o);
        }
        if (lane == 0) {
            g_packed[m].y     = __float_as_int(s0);
            g_packed[m + 1].y = __float_as_int(s1);
        }
    }
    if (m < e) {
        int j0 = g_packed[m].x >> 11;
        const uint4* u0 = (const uint4*)(g_udTh + (size_t)j0 * DDIM);
        float s0 = dot24(a, u0, lane);
#pragma unroll
        for (int o = 16; o; o >>= 1) s0 += __shfl_xor_sync(0xffffffffu, s0, o);
        if (lane == 0) g_packed[m].y = __float_as_int(s0);
    }
}

// ================================================================
// K3: SpMM. out[n,i] = sum_{m in group(i)} values[m] * XT[j_m, n].
// 256 threads, 4 consecutive n per thread, ITILE=4 i-rows, grid 4096.
// No smem staging: packed {offset,value} read via uniform LDG;
// 4 connections software-pipelined per step (MLP=4 gathers).
// ================================================================
#define ITILE 4
#define NTHR  256

__global__ __launch_bounds__(NTHR) void k3_spmm(float* __restrict__ out) {
    int i0 = blockIdx.x * ITILE;
    int n0 = threadIdx.x * 4;

    int rs[ITILE + 1];
#pragma unroll
    for (int k = 0; k <= ITILE; k++) rs[k] = __ldg(&g_rowstart[i0 + k]);

    const char* xbase = (const char*)g_XTh + n0 * 2;

    float4 acc[ITILE];
#pragma unroll
    for (int k = 0; k < ITILE; k++) acc[k] = make_float4(0.f, 0.f, 0.f, 0.f);

#pragma unroll
    for (int il = 0; il < ITILE; il++) {
        int m  = rs[il];
        int me = rs[il + 1];
        // batches of 4 connections: issue all loads, then consume
        for (; m + 4 <= me; m += 4) {
            int2 e0 = __ldg(&g_packed[m]);
            int2 e1 = __ldg(&g_packed[m + 1]);
            int2 e2 = __ldg(&g_packed[m + 2]);
            int2 e3 = __ldg(&g_packed[m + 3]);
            uint2 u0 = *(const uint2*)(xbase + e0.x);
            uint2 u1 = *(const uint2*)(xbase + e1.x);
            uint2 u2 = *(const uint2*)(xbase + e2.x);
            uint2 u3 = *(const uint2*)(xbase + e3.x);
            {
                float v = __int_as_float(e0.y);
                float2 f0 = __half22float2(*(const __half2*)&u0.x);
                float2 f1 = __half22float2(*(const __half2*)&u0.y);
                acc[il].x += v * f0.x; acc[il].y += v * f0.y;
                acc[il].z += v * f1.x; acc[il].w += v * f1.y;
            }
            {
                float v = __int_as_float(e1.y);
                float2 f0 = __half22float2(*(const __half2*)&u1.x);
                float2 f1 = __half22float2(*(const __half2*)&u1.y);
                acc[il].x += v * f0.x; acc[il].y += v * f0.y;
                acc[il].z += v * f1.x; acc[il].w += v * f1.y;
            }
            {
                float v = __int_as_float(e2.y);
                float2 f0 = __half22float2(*(const __half2*)&u2.x);
                float2 f1 = __half22float2(*(const __half2*)&u2.y);
                acc[il].x += v * f0.x; acc[il].y += v * f0.y;
                acc[il].z += v * f1.x; acc[il].w += v * f1.y;
            }
            {
                float v = __int_as_float(e3.y);
                float2 f0 = __half22float2(*(const __half2*)&u3.x);
                float2 f1 = __half22float2(*(const __half2*)&u3.y);
                acc[il].x += v * f0.x; acc[il].y += v * f0.y;
                acc[il].z += v * f1.x; acc[il].w += v * f1.y;
            }
        }
        for (; m < me; m++) {
            int2 e = __ldg(&g_packed[m]);
            uint2 u = *(const uint2*)(xbase + e.x);
            float v = __int_as_float(e.y);
            float2 f0 = __half22float2(*(const __half2*)&u.x);
            float2 f1 = __half22float2(*(const __half2*)&u.y);
            acc[il].x += v * f0.x; acc[il].y += v * f0.y;
            acc[il].z += v * f1.x; acc[il].w += v * f1.y;
        }
    }

    // Write 4 contiguous i-outputs (one float4) per owned n row
#pragma unroll
    for (int r = 0; r < 4; r++) {
        const float* s0 = (const float*)&acc[0];
        const float* s1 = (const float*)&acc[1];
        const float* s2 = (const float*)&acc[2];
        const float* s3 = (const float*)&acc[3];
        *(float4*)(out + (size_t)(n0 + r) * FDIM + i0) =
            make_float4(s0[r], s1[r], s2[r], s3[r]);
    }
}

// ---------------------------------------------------------------
extern "C" void kernel_launch(void* const* d_in, const int* in_sizes, int n_in,
                              void* d_out, int out_size) {
    const float* up_facts = (const float*)d_in[0];   // [NB, F]
    const float* down_enc = (const float*)d_in[1];   // [F, D]
    const float* up_dec   = (const float*)d_in[2];   // [D, F]
    const void*  ii       = d_in[3];                 // [M] sorted (int32 or int64)
    const void*  jj       = d_in[4];                 // [M]
    float* out = (float*)d_out;                      // [NB, F]

    k1_prep<<<K1_TOT, 256>>>(up_dec, ii, jj);
    k2_xt<<<16384, 256>>>(up_facts);              // (FDIM/32)*(NB/32)
    k2_values<<<FDIM / 8, 256>>>(down_enc);
    k3_spmm<<<FDIM / ITILE, NTHR>>>(out);
}

// round 11
// speedup vs baseline: 1.0660x; 1.0660x over previous
#include <cuda_runtime.h>
#include <cuda_fp16.h>
#include <stdint.h>

// Problem dims (fixed by the dataset)
#define FDIM 16384   // n_features
#define DDIM 768     // d_model
#define NB   1024    // B*S
#define MCONN 262144 // n_connections

// -------- scratch (device globals; no allocation allowed) --------
__device__ __half g_udTh[(size_t)FDIM * DDIM]; // up_decoder^T fp16: [F, D] (~25 MB)
__device__ __half g_XTh[(size_t)FDIM * NB];    // up_facts^T fp16:   [F, NB] (~33 MB)
__device__ int2   g_packed[MCONN];             // {xt byte offset = j*2048, value bits}
__device__ int    g_rowstart[FDIM + 1];        // CSR offsets over sorted i

// ---------------------------------------------------------------
// Inline int64-vs-int32 detection on the i_indices buffer (values
// < 16384 => odd int32-words of an int64 array are all zero; for
// int32 data the probed words are sorted indices ~8192 != 0).
// ---------------------------------------------------------------
__device__ __forceinline__ int detect_is64(const int* raw) {
    int q = MCONN / 4;
    int nz = 0;
#pragma unroll
    for (int k = 0; k < 8; k++) nz |= raw[2 * (q + k) + 1];
    return nz ? 0 : 1;
}

__device__ __forceinline__ int idx_at(const void* p, int is64, int m) {
    return is64 ? (int)((const long long*)p)[m] : ((const int*)p)[m];
}

// ================================================================
// K1: fused prep = transpose_ud | csr_scatter | j -> packed offset
// ================================================================
#define K1_UD   12288   // (FDIM/32)*(DDIM/32) = 512*24
#define K1_CSR  (K1_UD + 1024)
#define K1_TOT  (K1_CSR + 1024)

__global__ __launch_bounds__(256) void k1_prep(const float* __restrict__ up_dec,
                                               const void* __restrict__ ii,
                                               const void* __restrict__ jj) {
    int b = blockIdx.x;
    if (b < K1_UD) {
        __shared__ float tile[32][33];
        int bx = b & 511;          // F tile
        int by = b >> 9;           // D tile
        int c0 = bx * 32, r0 = by * 32;
        int tx = threadIdx.x & 31, ty = threadIdx.x >> 5;   // (32, 8)
#pragma unroll
        for (int k = 0; k < 32; k += 8)
            tile[ty + k][tx] = __ldcs(&up_dec[(size_t)(r0 + ty + k) * FDIM + (c0 + tx)]);
        __syncthreads();
#pragma unroll
        for (int k = 0; k < 32; k += 8)
            g_udTh[(size_t)(c0 + ty + k) * DDIM + (r0 + tx)] = __float2half(tile[tx][ty + k]);
    } else if (b < K1_CSR) {
        int m = (b - K1_UD) * 256 + threadIdx.x;
        int is64 = detect_is64((const int*)ii);
        int cur = idx_at(ii, is64, m);
        int prev = (m == 0) ? -1 : idx_at(ii, is64, m - 1);
        for (int i = prev + 1; i <= cur; i++) g_rowstart[i] = m;
        if (m == MCONN - 1)
            for (int i = cur + 1; i <= FDIM; i++) g_rowstart[i] = MCONN;
    } else {
        int m = (b - K1_CSR) * 256 + threadIdx.x;
        int is64 = detect_is64((const int*)ii);
        g_packed[m].x = idx_at(jj, is64, m) << 11;   // j * NB * sizeof(half)
    }
}

// ================================================================
// K2a: up_facts [NB,F] -> g_XTh [F,NB] fp16 (streaming reads)
// ================================================================
__global__ __launch_bounds__(256) void k2_xt(const float* __restrict__ up_facts) {
    __shared__ float tile[32][33];
    int bx = blockIdx.x & 511;     // F tile
    int by = blockIdx.x >> 9;      // NB tile
    int c0 = bx * 32, r0 = by * 32;
    int tx = threadIdx.x & 31, ty = threadIdx.x >> 5;
#pragma unroll
    for (int k = 0; k < 32; k += 8)
        tile[ty + k][tx] = __ldcs(&up_facts[(size_t)(r0 + ty + k) * FDIM + (c0 + tx)]);
    __syncthreads();
#pragma unroll
    for (int k = 0; k < 32; k += 8)
        g_XTh[(size_t)(c0 + ty + k) * NB + (r0 + tx)] = __float2half(tile[tx][ty + k]);
}

// ================================================================
// K2b: values[m] = <down_encoder[i_m,:], udT[j_m,:]> (fp16 gather,
// fp32 accumulate). One warp per i-group; de row in registers.
// Simple per-connection loop (R6 structure), writes g_packed[].y.
// ================================================================
__global__ __launch_bounds__(256) void k2_values(const float* __restrict__ de) {
    int warp = blockIdx.x * 8 + (threadIdx.x >> 5);
    int lane = threadIdx.x & 31;
    int i = warp;
    int s = g_rowstart[i];
    int e = g_rowstart[i + 1];
    if (s == e) return;

    // Cache de[i,:] lane slice: elements 8*(2*lane+64k) .. +7, k<3
    float a[3][8];
    const float4* dev = (const float4*)(de + (size_t)i * DDIM);
#pragma unroll
    for (int k = 0; k < 3; k++) {
        float4 p = dev[2 * lane + 64 * k];
        float4 q = dev[2 * lane + 64 * k + 1];
        a[k][0] = p.x; a[k][1] = p.y; a[k][2] = p.z; a[k][3] = p.w;
        a[k][4] = q.x; a[k][5] = q.y; a[k][6] = q.z; a[k][7] = q.w;
    }

    for (int m = s; m < e; m++) {
        int j = g_packed[m].x >> 11;
        const uint4* u = (const uint4*)(g_udTh + (size_t)j * DDIM);
        float sum = 0.f;
#pragma unroll
        for (int k = 0; k < 3; k++) {
            uint4 bb = u[lane + 32 * k];
            const __half2* h = (const __half2*)&bb;
#pragma unroll
            for (int t = 0; t < 4; t++) {
                float2 f = __half22float2(h[t]);
                sum += a[k][2 * t] * f.x + a[k][2 * t + 1] * f.y;
            }
        }
#pragma unroll
        for (int o = 16; o; o >>= 1) sum += __shfl_xor_sync(0xffffffffu, sum, o);
        if (lane == 0) g_packed[m].y = __float_as_int(sum);
    }
}

// ================================================================
// K3: SpMM. out[n,i] = sum_{m in group(i)} values[m] * XT[j_m, n].
// 256 threads, 4 consecutive n per thread, ITILE=4 i-rows, grid 4096.
// Packed entries staged in SMEM once per tile (CHUNK=256 covers
// the whole tile in virtually all cases), so the inner chain is
// LDS(29cyc) -> LDG gather, batched 4-wide for MLP=4.
// ================================================================
#define ITILE 4
#define NTHR  256
#define CHUNK 256

__global__ __launch_bounds__(NTHR) void k3_spmm(float* __restrict__ out) {
    __shared__ int2 se[CHUNK];
    __shared__ int  soff[ITILE + 1];

    int i0 = blockIdx.x * ITILE;
    int n0 = threadIdx.x * 4;

    if (threadIdx.x <= ITILE) soff[threadIdx.x] = g_rowstart[i0 + threadIdx.x];
    __syncthreads();

    int mbase = soff[0];
    int mend  = soff[ITILE];

    const char* xbase = (const char*)g_XTh + n0 * 2;

    float4 acc[ITILE];
#pragma unroll
    for (int k = 0; k < ITILE; k++) acc[k] = make_float4(0.f, 0.f, 0.f, 0.f);

    for (int cb = mbase; cb < mend; cb += CHUNK) {
        int cend = min(cb + CHUNK, mend);
        __syncthreads();
        if (cb + (int)threadIdx.x < cend)
            se[threadIdx.x] = g_packed[cb + threadIdx.x];
        __syncthreads();

#pragma unroll
        for (int il = 0; il < ITILE; il++) {
            int ms = max(soff[il], cb) - cb;
            int me = min(soff[il + 1], cend) - cb;
            int m = ms;
            for (; m + 4 <= me; m += 4) {
                int2 e0 = se[m];
                int2 e1 = se[m + 1];
                int2 e2 = se[m + 2];
                int2 e3 = se[m + 3];
                uint2 u0 = *(const uint2*)(xbase + e0.x);
                uint2 u1 = *(const uint2*)(xbase + e1.x);
                uint2 u2 = *(const uint2*)(xbase + e2.x);
                uint2 u3 = *(const uint2*)(xbase + e3.x);
                {
                    float v = __int_as_float(e0.y);
                    float2 f0 = __half22float2(*(const __half2*)&u0.x);
                    float2 f1 = __half22float2(*(const __half2*)&u0.y);
                    acc[il].x += v * f0.x; acc[il].y += v * f0.y;
                    acc[il].z += v * f1.x; acc[il].w += v * f1.y;
                }
                {
                    float v = __int_as_float(e1.y);
                    float2 f0 = __half22float2(*(const __half2*)&u1.x);
                    float2 f1 = __half22float2(*(const __half2*)&u1.y);
                    acc[il].x += v * f0.x; acc[il].y += v * f0.y;
                    acc[il].z += v * f1.x; acc[il].w += v * f1.y;
                }
                {
                    float v = __int_as_float(e2.y);
                    float2 f0 = __half22float2(*(const __half2*)&u2.x);
                    float2 f1 = __half22float2(*(const __half2*)&u2.y);
                    acc[il].x += v * f0.x; acc[il].y += v * f0.y;
                    acc[il].z += v * f1.x; acc[il].w += v * f1.y;
                }
                {
                    float v = __int_as_float(e3.y);
                    float2 f0 = __half22float2(*(const __half2*)&u3.x);
                    float2 f1 = __half22float2(*(const __half2*)&u3.y);
                    acc[il].x += v * f0.x; acc[il].y += v * f0.y;
                    acc[il].z += v * f1.x; acc[il].w += v * f1.y;
                }
            }
            for (; m < me; m++) {
                int2 e = se[m];
                uint2 u = *(const uint2*)(xbase + e.x);
                float v = __int_as_float(e.y);
                float2 f0 = __half22float2(*(const __half2*)&u.x);
                float2 f1 = __half22float2(*(const __half2*)&u.y);
                acc[il].x += v * f0.x; acc[il].y += v * f0.y;
                acc[il].z += v * f1.x; acc[il].w += v * f1.y;
            }
        }
    }

    // Write 4 contiguous i-outputs (one float4) per owned n row
#pragma unroll
    for (int r = 0; r < 4; r++) {
        const float* s0 = (const float*)&acc[0];
        const float* s1 = (const float*)&acc[1];
        const float* s2 = (const float*)&acc[2];
        const float* s3 = (const float*)&acc[3];
        *(float4*)(out + (size_t)(n0 + r) * FDIM + i0) =
            make_float4(s0[r], s1[r], s2[r], s3[r]);
    }
}

// ---------------------------------------------------------------
extern "C" void kernel_launch(void* const* d_in, const int* in_sizes, int n_in,
                              void* d_out, int out_size) {
    const float* up_facts = (const float*)d_in[0];   // [NB, F]
    const float* down_enc = (const float*)d_in[1];   // [F, D]
    const float* up_dec   = (const float*)d_in[2];   // [D, F]
    const void*  ii       = d_in[3];                 // [M] sorted (int32 or int64)
    const void*  jj       = d_in[4];                 // [M]
    float* out = (float*)d_out;                      // [NB, F]

    k1_prep<<<K1_TOT, 256>>>(up_dec, ii, jj);
    k2_xt<<<16384, 256>>>(up_facts);              // (FDIM/32)*(NB/32)
    k2_values<<<FDIM / 8, 256>>>(down_enc);
    k3_spmm<<<FDIM / ITILE, NTHR>>>(out);
}

// round 12
// speedup vs baseline: 1.0702x; 1.0040x over previous
#include <cuda_runtime.h>
#include <cuda_fp16.h>
#include <stdint.h>

// Problem dims (fixed by the dataset)
#define FDIM 16384   // n_features
#define DDIM 768     // d_model
#define NB   1024    // B*S
#define MCONN 262144 // n_connections

// -------- scratch (device globals; no allocation allowed) --------
__device__ __half g_udTh[(size_t)FDIM * DDIM]; // up_decoder^T fp16: [F, D] (~25 MB)
__device__ __half g_XTh[(size_t)FDIM * NB];    // up_facts^T fp16:   [F, NB] (~33 MB)
__device__ int2   g_packed[MCONN];             // {xt byte offset = j*2048, value bits}
__device__ int    g_rowstart[FDIM + 1];        // CSR offsets over sorted i

// ---------------------------------------------------------------
// Inline int64-vs-int32 detection on the i_indices buffer (values
// < 16384 => odd int32-words of an int64 array are all zero; for
// int32 data the probed words are sorted indices ~8192 != 0).
// ---------------------------------------------------------------
__device__ __forceinline__ int detect_is64(const int* raw) {
    int q = MCONN / 4;
    int nz = 0;
#pragma unroll
    for (int k = 0; k < 8; k++) nz |= raw[2 * (q + k) + 1];
    return nz ? 0 : 1;
}

__device__ __forceinline__ int idx_at(const void* p, int is64, int m) {
    return is64 ? (int)((const long long*)p)[m] : ((const int*)p)[m];
}

// ================================================================
// K1: fused prep = transpose_ud | transpose_x | csr_scatter | jconv
//   blocks [0, 12288)          : up_decoder [D,F] -> g_udTh [F,D]
//   blocks [12288, 28672)      : up_facts [NB,F] -> g_XTh [F,NB]
//   blocks [28672, 29696)      : CSR row offsets (O(M) scatter)
//   blocks [29696, 30720)      : j -> packed byte offset
// ================================================================
#define K1_UD   12288                 // (FDIM/32)*(DDIM/32) = 512*24
#define K1_XT   (K1_UD + 16384)      // + (FDIM/32)*(NB/32) = 512*32
#define K1_CSR  (K1_XT + 1024)
#define K1_TOT  (K1_CSR + 1024)

__global__ __launch_bounds__(256) void k1_prep(const float* __restrict__ up_dec,
                                               const float* __restrict__ up_facts,
                                               const void* __restrict__ ii,
                                               const void* __restrict__ jj) {
    int b = blockIdx.x;
    if (b < K1_UD) {
        __shared__ float tile[32][33];
        int bx = b & 511;          // F tile
        int by = b >> 9;           // D tile
        int c0 = bx * 32, r0 = by * 32;
        int tx = threadIdx.x & 31, ty = threadIdx.x >> 5;   // (32, 8)
#pragma unroll
        for (int k = 0; k < 32; k += 8)
            tile[ty + k][tx] = __ldcs(&up_dec[(size_t)(r0 + ty + k) * FDIM + (c0 + tx)]);
        __syncthreads();
#pragma unroll
        for (int k = 0; k < 32; k += 8)
            g_udTh[(size_t)(c0 + ty + k) * DDIM + (r0 + tx)] = __float2half(tile[tx][ty + k]);
    } else if (b < K1_XT) {
        __shared__ float tile[32][33];
        int b2 = b - K1_UD;
        int bx = b2 & 511;         // F tile
        int by = b2 >> 9;          // NB tile
        int c0 = bx * 32, r0 = by * 32;
        int tx = threadIdx.x & 31, ty = threadIdx.x >> 5;
#pragma unroll
        for (int k = 0; k < 32; k += 8)
            tile[ty + k][tx] = __ldcs(&up_facts[(size_t)(r0 + ty + k) * FDIM + (c0 + tx)]);
        __syncthreads();
#pragma unroll
        for (int k = 0; k < 32; k += 8)
            g_XTh[(size_t)(c0 + ty + k) * NB + (r0 + tx)] = __float2half(tile[tx][ty + k]);
    } else if (b < K1_CSR) {
        int m = (b - K1_XT) * 256 + threadIdx.x;
        int is64 = detect_is64((const int*)ii);
        int cur = idx_at(ii, is64, m);
        int prev = (m == 0) ? -1 : idx_at(ii, is64, m - 1);
        for (int i = prev + 1; i <= cur; i++) g_rowstart[i] = m;
        if (m == MCONN - 1)
            for (int i = cur + 1; i <= FDIM; i++) g_rowstart[i] = MCONN;
    } else {
        int m = (b - K1_CSR) * 256 + threadIdx.x;
        int is64 = detect_is64((const int*)ii);
        g_packed[m].x = idx_at(jj, is64, m) << 11;   // j * NB * sizeof(half)
    }
}

// ================================================================
// K2: values[m] = <down_encoder[i_m,:], udT[j_m,:]> (fp16 gather,
// fp32 accumulate). One warp per i-group; de row in registers.
// ================================================================
__global__ __launch_bounds__(256) void k2_values(const float* __restrict__ de) {
    int warp = blockIdx.x * 8 + (threadIdx.x >> 5);
    int lane = threadIdx.x & 31;
    int i = warp;
    int s = g_rowstart[i];
    int e = g_rowstart[i + 1];
    if (s == e) return;

    // Cache de[i,:] lane slice: elements 8*(2*lane+64k) .. +7, k<3
    float a[3][8];
    const float4* dev = (const float4*)(de + (size_t)i * DDIM);
#pragma unroll
    for (int k = 0; k < 3; k++) {
        float4 p = dev[2 * lane + 64 * k];
        float4 q = dev[2 * lane + 64 * k + 1];
        a[k][0] = p.x; a[k][1] = p.y; a[k][2] = p.z; a[k][3] = p.w;
        a[k][4] = q.x; a[k][5] = q.y; a[k][6] = q.z; a[k][7] = q.w;
    }

    for (int m = s; m < e; m++) {
        int j = g_packed[m].x >> 11;
        const uint4* u = (const uint4*)(g_udTh + (size_t)j * DDIM);
        float sum = 0.f;
#pragma unroll
        for (int k = 0; k < 3; k++) {
            uint4 bb = u[lane + 32 * k];
            const __half2* h = (const __half2*)&bb;
#pragma unroll
            for (int t = 0; t < 4; t++) {
                float2 f = __half22float2(h[t]);
                sum += a[k][2 * t] * f.x + a[k][2 * t + 1] * f.y;
            }
        }
#pragma unroll
        for (int o = 16; o; o >>= 1) sum += __shfl_xor_sync(0xffffffffu, sum, o);
        if (lane == 0) g_packed[m].y = __float_as_int(sum);
    }
}

// ================================================================
// K3: SpMM. out[n,i] = sum_{m in group(i)} values[m] * XT[j_m, n].
// 128 threads, 8 consecutive n per thread (one 16B gather per
// connection), ITILE=4 i-rows, grid 4096. Packed entries staged
// in SMEM once per tile; inner chain LDS -> LDG.128, 4-wide MLP.
// ================================================================
#define ITILE 4
#define NTHR  128
#define CHUNK 256

__device__ __forceinline__ void fma8(float acc[8], float v, uint4 u) {
    const __half2* h = (const __half2*)&u;
#pragma unroll
    for (int t = 0; t < 4; t++) {
        float2 f = __half22float2(h[t]);
        acc[2 * t]     += v * f.x;
        acc[2 * t + 1] += v * f.y;
    }
}

__global__ __launch_bounds__(NTHR) void k3_spmm(float* __restrict__ out) {
    __shared__ int2 se[CHUNK];
    __shared__ int  soff[ITILE + 1];

    int i0 = blockIdx.x * ITILE;
    int n0 = threadIdx.x * 8;

    if (threadIdx.x <= ITILE) soff[threadIdx.x] = g_rowstart[i0 + threadIdx.x];
    __syncthreads();

    int mbase = soff[0];
    int mend  = soff[ITILE];

    const char* xbase = (const char*)g_XTh + n0 * 2;

    float acc[ITILE][8];
#pragma unroll
    for (int k = 0; k < ITILE; k++)
#pragma unroll
        for (int r = 0; r < 8; r++) acc[k][r] = 0.f;

    for (int cb = mbase; cb < mend; cb += CHUNK) {
        int cend = min(cb + CHUNK, mend);
        __syncthreads();
        for (int t = threadIdx.x; cb + t < cend; t += NTHR)
            se[t] = g_packed[cb + t];
        __syncthreads();

#pragma unroll
        for (int il = 0; il < ITILE; il++) {
            int ms = max(soff[il], cb) - cb;
            int me = min(soff[il + 1], cend) - cb;
            int m = ms;
            for (; m + 4 <= me; m += 4) {
                int2 e0 = se[m];
                int2 e1 = se[m + 1];
                int2 e2 = se[m + 2];
                int2 e3 = se[m + 3];
                uint4 u0 = *(const uint4*)(xbase + e0.x);
                uint4 u1 = *(const uint4*)(xbase + e1.x);
                uint4 u2 = *(const uint4*)(xbase + e2.x);
                uint4 u3 = *(const uint4*)(xbase + e3.x);
                fma8(acc[il], __int_as_float(e0.y), u0);
                fma8(acc[il], __int_as_float(e1.y), u1);
                fma8(acc[il], __int_as_float(e2.y), u2);
                fma8(acc[il], __int_as_float(e3.y), u3);
            }
            for (; m < me; m++) {
                int2 e = se[m];
                uint4 u = *(const uint4*)(xbase + e.x);
                fma8(acc[il], __int_as_float(e.y), u);
            }
        }
    }

    // Write 4 contiguous i-outputs (one float4) per owned n row
#pragma unroll
    for (int r = 0; r < 8; r++) {
        *(float4*)(out + (size_t)(n0 + r) * FDIM + i0) =
            make_float4(acc[0][r], acc[1][r], acc[2][r], acc[3][r]);
    }
}

// ---------------------------------------------------------------
extern "C" void kernel_launch(void* const* d_in, const int* in_sizes, int n_in,
                              void* d_out, int out_size) {
    const float* up_facts = (const float*)d_in[0];   // [NB, F]
    const float* down_enc = (const float*)d_in[1];   // [F, D]
    const float* up_dec   = (const float*)d_in[2];   // [D, F]
    const void*  ii       = d_in[3];                 // [M] sorted (int32 or int64)
    const void*  jj       = d_in[4];                 // [M]
    float* out = (float*)d_out;                      // [NB, F]

    k1_prep<<<K1_TOT, 256>>>(up_dec, up_facts, ii, jj);
    k2_values<<<FDIM / 8, 256>>>(down_enc);
    k3_spmm<<<FDIM / ITILE, NTHR>>>(out);
}

// round 14
// speedup vs baseline: 1.0796x; 1.0088x over previous
#include <cuda_runtime.h>
#include <cuda_fp16.h>
#include <stdint.h>

// Problem dims (fixed by the dataset)
#define FDIM 16384   // n_features
#define DDIM 768     // d_model
#define NB   1024    // B*S
#define MCONN 262144 // n_connections

// -------- scratch (device globals; no allocation allowed) --------
__device__ __half g_udTh[(size_t)FDIM * DDIM]; // up_decoder^T fp16: [F, D] (~25 MB)
__device__ __half g_XTh[(size_t)FDIM * NB];    // up_facts^T fp16:   [F, NB] (~33 MB)
__device__ int2   g_packed[MCONN];             // {xt byte offset = j*2048, value bits}
__device__ int    g_rowstart[FDIM + 1];        // CSR offsets over sorted i

// ---------------------------------------------------------------
// Inline int64-vs-int32 detection on the i_indices buffer (values
// < 16384 => odd int32-words of an int64 array are all zero; for
// int32 data the probed words are sorted indices ~8192 != 0).
// ---------------------------------------------------------------
__device__ __forceinline__ int detect_is64(const int* raw) {
    int q = MCONN / 4;
    int nz = 0;
#pragma unroll
    for (int k = 0; k < 8; k++) nz |= raw[2 * (q + k) + 1];
    return nz ? 0 : 1;
}

__device__ __forceinline__ int idx_at(const void* p, int is64, int m) {
    return is64 ? (int)((const long long*)p)[m] : ((const int*)p)[m];
}

// ================================================================
// K1: fused prep = transpose_ud | transpose_x | csr_scatter | jconv
// Transpose store phase vectorized: 2 x half2 per thread.
// ================================================================
#define K1_UD   12288                 // (FDIM/32)*(DDIM/32) = 512*24
#define K1_XT   (K1_UD + 16384)      // + (FDIM/32)*(NB/32) = 512*32
#define K1_CSR  (K1_XT + 1024)
#define K1_TOT  (K1_CSR + 1024)

__global__ __launch_bounds__(256) void k1_prep(const float* __restrict__ up_dec,
                                               const float* __restrict__ up_facts,
                                               const void* __restrict__ ii,
                                               const void* __restrict__ jj) {
    int b = blockIdx.x;
    if (b < K1_XT) {
        // ---- transpose section ----
        __shared__ float tile[32][33];
        const float* src;
        __half* dst;
        int c0, r0, ostride;
        if (b < K1_UD) {
            int bx = b & 511, by = b >> 9;        // F tile, D tile
            c0 = bx * 32; r0 = by * 32;
            src = up_dec; dst = g_udTh; ostride = DDIM;
        } else {
            int b2 = b - K1_UD;
            int bx = b2 & 511, by = b2 >> 9;      // F tile, NB tile
            c0 = bx * 32; r0 = by * 32;
            src = up_facts; dst = g_XTh; ostride = NB;
        }
        int tx = threadIdx.x & 31, ty = threadIdx.x >> 5;   // (32, 8)
#pragma unroll
        for (int k = 0; k < 32; k += 8)
            tile[ty + k][tx] = __ldcs(&src[(size_t)(r0 + ty + k) * FDIM + (c0 + tx)]);
        __syncthreads();
        // store: 32 f-rows x 16 half2 = 512 half2, 2 per thread
#pragma unroll
        for (int k = 0; k < 2; k++) {
            int idx = threadIdx.x + k * 256;
            int fy  = idx >> 4;          // f row within tile
            int rx2 = idx & 15;          // half2 index along r
            __half2 v = __floats2half2_rn(tile[2 * rx2][fy], tile[2 * rx2 + 1][fy]);
            *(__half2*)&dst[(size_t)(c0 + fy) * ostride + r0 + 2 * rx2] = v;
        }
    } else if (b < K1_CSR) {
        int m = (b - K1_XT) * 256 + threadIdx.x;
        int is64 = detect_is64((const int*)ii);
        int cur = idx_at(ii, is64, m);
        int prev = (m == 0) ? -1 : idx_at(ii, is64, m - 1);
        for (int i = prev + 1; i <= cur; i++) g_rowstart[i] = m;
        if (m == MCONN - 1)
            for (int i = cur + 1; i <= FDIM; i++) g_rowstart[i] = MCONN;
    } else {
        int m = (b - K1_CSR) * 256 + threadIdx.x;
        int is64 = detect_is64((const int*)ii);
        g_packed[m].x = idx_at(jj, is64, m) << 11;   // j * NB * sizeof(half)
    }
}

// ================================================================
// K2: values[m] = <down_encoder[i_m,:], udT[j_m,:]>.
// One warp per i-group; de row in registers; 2 connections in
// flight (6 independent LDG.128), interleaved shuffle reductions.
// ================================================================
__device__ __forceinline__ float dot24p(const float a[3][8],
                                        uint4 b0, uint4 b1, uint4 b2) {
    float sum = 0.f;
    uint4 bs[3] = {b0, b1, b2};
#pragma unroll
    for (int k = 0; k < 3; k++) {
        const __half2* h = (const __half2*)&bs[k];
#pragma unroll
        for (int t = 0; t < 4; t++) {
            float2 f = __half22float2(h[t]);
            sum += a[k][2 * t] * f.x + a[k][2 * t + 1] * f.y;
        }
    }
    return sum;
}

__global__ __launch_bounds__(256) void k2_values(const float* __restrict__ de) {
    int warp = blockIdx.x * 8 + (threadIdx.x >> 5);
    int lane = threadIdx.x & 31;
    int i = warp;
    int s = g_rowstart[i];
    int e = g_rowstart[i + 1];
    if (s == e) return;

    // Cache de[i,:] lane slice: elements 8*(2*lane+64k) .. +7, k<3
    float a[3][8];
    const float4* dev = (const float4*)(de + (size_t)i * DDIM);
#pragma unroll
    for (int k = 0; k < 3; k++) {
        float4 p = dev[2 * lane + 64 * k];
        float4 q = dev[2 * lane + 64 * k + 1];
        a[k][0] = p.x; a[k][1] = p.y; a[k][2] = p.z; a[k][3] = p.w;
        a[k][4] = q.x; a[k][5] = q.y; a[k][6] = q.z; a[k][7] = q.w;
    }

    int m = s;
    for (; m + 2 <= e; m += 2) {
        int j0 = g_packed[m].x >> 11;
        int j1 = g_packed[m + 1].x >> 11;
        const uint4* u0 = (const uint4*)(g_udTh + (size_t)j0 * DDIM);
        const uint4* u1 = (const uint4*)(g_udTh + (size_t)j1 * DDIM);
        uint4 b00 = u0[lane], b01 = u0[lane + 32], b02 = u0[lane + 64];
        uint4 b10 = u1[lane], b11 = u1[lane + 32], b12 = u1[lane + 64];
        float s0 = dot24p(a, b00, b01, b02);
        float s1 = dot24p(a, b10, b11, b12);
#pragma unroll
        for (int o = 16; o; o >>= 1) {
            s0 += __shfl_xor_sync(0xffffffffu, s0, o);
            s1 += __shfl_xor_sync(0xffffffffu, s1, o);
        }
        if (lane == 0) {
            g_packed[m].y     = __float_as_int(s0);
            g_packed[m + 1].y = __float_as_int(s1);
        }
    }
    if (m < e) {
        int j0 = g_packed[m].x >> 11;
        const uint4* u0 = (const uint4*)(g_udTh + (size_t)j0 * DDIM);
        float s0 = dot24p(a, u0[lane], u0[lane + 32], u0[lane + 64]);
#pragma unroll
        for (int o = 16; o; o >>= 1) s0 += __shfl_xor_sync(0xffffffffu, s0, o);
        if (lane == 0) g_packed[m].y = __float_as_int(s0);
    }
}

// ================================================================
// K3: SpMM. out[n,i] = sum_{m in group(i)} values[m] * XT[j_m, n].
// 128 threads, 8 consecutive n per thread (16B gather/connection),
// ITILE=4, grid 4096. Packed entries staged in SMEM once per tile;
// gathers batched 8-wide (MLP=8).
// ================================================================
#define ITILE 4
#define NTHR  128
#define CHUNK 256

__device__ __forceinline__ void fma8(float acc[8], float v, uint4 u) {
    const __half2* h = (const __half2*)&u;
#pragma unroll
    for (int t = 0; t < 4; t++) {
        float2 f = __half22float2(h[t]);
        acc[2 * t]     += v * f.x;
        acc[2 * t + 1] += v * f.y;
    }
}

__global__ __launch_bounds__(NTHR) void k3_spmm(float* __restrict__ out) {
    __shared__ int2 se[CHUNK];
    __shared__ int  soff[ITILE + 1];

    int i0 = blockIdx.x * ITILE;
    int n0 = threadIdx.x * 8;

    if (threadIdx.x <= ITILE) soff[threadIdx.x] = g_rowstart[i0 + threadIdx.x];
    __syncthreads();

    int mbase = soff[0];
    int mend  = soff[ITILE];

    const char* xbase = (const char*)g_XTh + n0 * 2;

    float acc[ITILE][8];
#pragma unroll
    for (int k = 0; k < ITILE; k++)
#pragma unroll
        for (int r = 0; r < 8; r++) acc[k][r] = 0.f;

    for (int cb = mbase; cb < mend; cb += CHUNK) {
        int cend = min(cb + CHUNK, mend);
        __syncthreads();
        for (int t = threadIdx.x; cb + t < cend; t += NTHR)
            se[t] = g_packed[cb + t];
        __syncthreads();

#pragma unroll
        for (int il = 0; il < ITILE; il++) {
            int ms = max(soff[il], cb) - cb;
            int me = min(soff[il + 1], cend) - cb;
            int m = ms;
            for (; m + 8 <= me; m += 8) {
                int2 e0 = se[m],     e1 = se[m + 1], e2 = se[m + 2], e3 = se[m + 3];
                int2 e4 = se[m + 4], e5 = se[m + 5], e6 = se[m + 6], e7 = se[m + 7];
                uint4 u0 = *(const uint4*)(xbase + e0.x);
                uint4 u1 = *(const uint4*)(xbase + e1.x);
                uint4 u2 = *(const uint4*)(xbase + e2.x);
                uint4 u3 = *(const uint4*)(xbase + e3.x);
                uint4 u4 = *(const uint4*)(xbase + e4.x);
                uint4 u5 = *(const uint4*)(xbase + e5.x);
                uint4 u6 = *(const uint4*)(xbase + e6.x);
                uint4 u7 = *(const uint4*)(xbase + e7.x);
                fma8(acc[il], __int_as_float(e0.y), u0);
                fma8(acc[il], __int_as_float(e1.y), u1);
                fma8(acc[il], __int_as_float(e2.y), u2);
                fma8(acc[il], __int_as_float(e3.y), u3);
                fma8(acc[il], __int_as_float(e4.y), u4);
                fma8(acc[il], __int_as_float(e5.y), u5);
                fma8(acc[il], __int_as_float(e6.y), u6);
                fma8(acc[il], __int_as_float(e7.y), u7);
            }
            for (; m + 4 <= me; m += 4) {
                int2 e0 = se[m], e1 = se[m + 1], e2 = se[m + 2], e3 = se[m + 3];
                uint4 u0 = *(const uint4*)(xbase + e0.x);
                uint4 u1 = *(const uint4*)(xbase + e1.x);
                uint4 u2 = *(const uint4*)(xbase + e2.x);
                uint4 u3 = *(const uint4*)(xbase + e3.x);
                fma8(acc[il], __int_as_float(e0.y), u0);
                fma8(acc[il], __int_as_float(e1.y), u1);
                fma8(acc[il], __int_as_float(e2.y), u2);
                fma8(acc[il], __int_as_float(e3.y), u3);
            }
            for (; m < me; m++) {
                int2 e = se[m];
                uint4 u = *(const uint4*)(xbase + e.x);
                fma8(acc[il], __int_as_float(e.y), u);
            }
        }
    }

    // Write 4 contiguous i-outputs (one float4) per owned n row
#pragma unroll
    for (int r = 0; r < 8; r++) {
        *(float4*)(out + (size_t)(n0 + r) * FDIM + i0) =
            make_float4(acc[0][r], acc[1][r], acc[2][r], acc[3][r]);
    }
}

// ---------------------------------------------------------------
extern "C" void kernel_launch(void* const* d_in, const int* in_sizes, int n_in,
                              void* d_out, int out_size) {
    const float* up_facts = (const float*)d_in[0];   // [NB, F]
    const float* down_enc = (const float*)d_in[1];   // [F, D]
    const float* up_dec   = (const float*)d_in[2];   // [D, F]
    const void*  ii       = d_in[3];                 // [M] sorted (int32 or int64)
    const void*  jj       = d_in[4];                 // [M]
    float* out = (float*)d_out;                      // [NB, F]

    k1_prep<<<K1_TOT, 256>>>(up_dec, up_facts, ii, jj);
    k2_values<<<FDIM / 8, 256>>>(down_enc);
    k3_spmm<<<FDIM / ITILE, NTHR>>>(out);
}

// round 15
// speedup vs baseline: 1.1420x; 1.0578x over previous
#include <cuda_runtime.h>
#include <cuda_fp16.h>
#include <stdint.h>

// Problem dims (fixed by the dataset)
#define FDIM 16384   // n_features
#define DDIM 768     // d_model
#define NB   1024    // B*S
#define MCONN 262144 // n_connections

// -------- scratch (device globals; no allocation allowed) --------
__device__ __half g_udTh[(size_t)FDIM * DDIM]; // up_decoder^T fp16: [F, D] (~25 MB)
__device__ __half g_XTh[(size_t)FDIM * NB];    // up_facts^T fp16:   [F, NB] (~33 MB)
__device__ int2   g_packed[MCONN];             // {xt byte offset = j*2048, value bits}
__device__ int    g_rowstart[FDIM + 1];        // CSR offsets over sorted i

// ---------------------------------------------------------------
// Inline int64-vs-int32 detection on the i_indices buffer (values
// < 16384 => odd int32-words of an int64 array are all zero; for
// int32 data the probed words are sorted indices ~8192 != 0).
// ---------------------------------------------------------------
__device__ __forceinline__ int detect_is64(const int* raw) {
    int q = MCONN / 4;
    int nz = 0;
#pragma unroll
    for (int k = 0; k < 8; k++) nz |= raw[2 * (q + k) + 1];
    return nz ? 0 : 1;
}

__device__ __forceinline__ int idx_at(const void* p, int is64, int m) {
    return is64 ? (int)((const long long*)p)[m] : ((const int*)p)[m];
}

// ================================================================
// K1: fused prep = transpose_ud | transpose_x | csr_scatter | jconv
// Transpose: 32(r) x 128(f) tiles, float4 loads, pad-1 smem
// (conflict-free both phases), uint2 (4-half) stores.
//   ud: r = D rows (24 tiles), f = F cols (128 tiles)  -> 3072
//   xt: r = NB rows (32 tiles), f = F cols (128 tiles) -> 4096
// ================================================================
#define K1_UD   3072
#define K1_XT   (K1_UD + 4096)
#define K1_CSR  (K1_XT + 1024)
#define K1_TOT  (K1_CSR + 1024)

__global__ __launch_bounds__(256) void k1_prep(const float* __restrict__ up_dec,
                                               const float* __restrict__ up_facts,
                                               const void* __restrict__ ii,
                                               const void* __restrict__ jj) {
    int b = blockIdx.x;
    if (b < K1_XT) {
        __shared__ float tile[32 * 129];   // [r][f4*4+e], row stride 129
        const float* src;
        __half* dst;
        int c0, r0, ostride;
        if (b < K1_UD) {
            int fblk = b & 127, rblk = b >> 7;     // 128 F-tiles, 24 D-tiles
            c0 = fblk * 128; r0 = rblk * 32;
            src = up_dec; dst = g_udTh; ostride = DDIM;
        } else {
            int b2 = b - K1_UD;
            int fblk = b2 & 127, rblk = b2 >> 7;   // 128 F-tiles, 32 NB-tiles
            c0 = fblk * 128; r0 = rblk * 32;
            src = up_facts; dst = g_XTh; ostride = NB;
        }
        // ---- load phase: 32 rows x 32 float4; 4 float4 per thread ----
        int r  = threadIdx.x >> 3;          // 0..31
        int cb = threadIdx.x & 7;           // 0..7
        const float4* srow = (const float4*)(src + (size_t)(r0 + r) * FDIM + c0);
        float* trow = &tile[r * 129];
#pragma unroll
        for (int k = 0; k < 4; k++) {
            int c = cb + 8 * k;             // float4 index 0..31
            float4 v = __ldcs(&srow[c]);
            trow[4 * c + 0] = v.x;
            trow[4 * c + 1] = v.y;
            trow[4 * c + 2] = v.z;
            trow[4 * c + 3] = v.w;
        }
        __syncthreads();
        // ---- store phase: 128 fy x 8 r-quads; 4 uint2 per thread ----
#pragma unroll
        for (int k = 0; k < 4; k++) {
            int task = threadIdx.x + 256 * k;
            int fy = task >> 3;             // 0..127
            int rq = task & 7;              // 0..7  (covers r = 4*rq..+3)
            float f0 = tile[(4 * rq + 0) * 129 + fy];
            float f1 = tile[(4 * rq + 1) * 129 + fy];
            float f2 = tile[(4 * rq + 2) * 129 + fy];
            float f3 = tile[(4 * rq + 3) * 129 + fy];
            __half2 h0 = __floats2half2_rn(f0, f1);
            __half2 h1 = __floats2half2_rn(f2, f3);
            uint2 o;
            o.x = *(const unsigned*)&h0;
            o.y = *(const unsigned*)&h1;
            *(uint2*)&dst[(size_t)(c0 + fy) * ostride + r0 + 4 * rq] = o;
        }
    } else if (b < K1_CSR) {
        int m = (b - K1_XT) * 256 + threadIdx.x;
        int is64 = detect_is64((const int*)ii);
        int cur = idx_at(ii, is64, m);
        int prev = (m == 0) ? -1 : idx_at(ii, is64, m - 1);
        for (int i = prev + 1; i <= cur; i++) g_rowstart[i] = m;
        if (m == MCONN - 1)
            for (int i = cur + 1; i <= FDIM; i++) g_rowstart[i] = MCONN;
    } else {
        int m = (b - K1_CSR) * 256 + threadIdx.x;
        int is64 = detect_is64((const int*)ii);
        g_packed[m].x = idx_at(jj, is64, m) << 11;   // j * NB * sizeof(half)
    }
}

// ================================================================
// K2: values[m] = <down_encoder[i_m,:], udT[j_m,:]>.
// One warp per i-group; de row in registers; 2 connections in
// flight (6 independent LDG.128), interleaved shuffle reductions.
// ================================================================
__device__ __forceinline__ float dot24p(const float a[3][8],
                                        uint4 b0, uint4 b1, uint4 b2) {
    float sum = 0.f;
    uint4 bs[3] = {b0, b1, b2};
#pragma unroll
    for (int k = 0; k < 3; k++) {
        const __half2* h = (const __half2*)&bs[k];
#pragma unroll
        for (int t = 0; t < 4; t++) {
            float2 f = __half22float2(h[t]);
            sum += a[k][2 * t] * f.x + a[k][2 * t + 1] * f.y;
        }
    }
    return sum;
}

__global__ __launch_bounds__(256) void k2_values(const float* __restrict__ de) {
    int warp = blockIdx.x * 8 + (threadIdx.x >> 5);
    int lane = threadIdx.x & 31;
    int i = warp;
    int s = g_rowstart[i];
    int e = g_rowstart[i + 1];
    if (s == e) return;

    // Cache de[i,:] lane slice: elements 8*(2*lane+64k) .. +7, k<3
    float a[3][8];
    const float4* dev = (const float4*)(de + (size_t)i * DDIM);
#pragma unroll
    for (int k = 0; k < 3; k++) {
        float4 p = dev[2 * lane + 64 * k];
        float4 q = dev[2 * lane + 64 * k + 1];
        a[k][0] = p.x; a[k][1] = p.y; a[k][2] = p.z; a[k][3] = p.w;
        a[k][4] = q.x; a[k][5] = q.y; a[k][6] = q.z; a[k][7] = q.w;
    }

    int m = s;
    for (; m + 2 <= e; m += 2) {
        int j0 = g_packed[m].x >> 11;
        int j1 = g_packed[m + 1].x >> 11;
        const uint4* u0 = (const uint4*)(g_udTh + (size_t)j0 * DDIM);
        const uint4* u1 = (const uint4*)(g_udTh + (size_t)j1 * DDIM);
        uint4 b00 = u0[lane], b01 = u0[lane + 32], b02 = u0[lane + 64];
        uint4 b10 = u1[lane], b11 = u1[lane + 32], b12 = u1[lane + 64];
        float s0 = dot24p(a, b00, b01, b02);
        float s1 = dot24p(a, b10, b11, b12);
#pragma unroll
        for (int o = 16; o; o >>= 1) {
            s0 += __shfl_xor_sync(0xffffffffu, s0, o);
            s1 += __shfl_xor_sync(0xffffffffu, s1, o);
        }
        if (lane == 0) {
            g_packed[m].y     = __float_as_int(s0);
            g_packed[m + 1].y = __float_as_int(s1);
        }
    }
    if (m < e) {
        int j0 = g_packed[m].x >> 11;
        const uint4* u0 = (const uint4*)(g_udTh + (size_t)j0 * DDIM);
        float s0 = dot24p(a, u0[lane], u0[lane + 32], u0[lane + 64]);
#pragma unroll
        for (int o = 16; o; o >>= 1) s0 += __shfl_xor_sync(0xffffffffu, s0, o);
        if (lane == 0) g_packed[m].y = __float_as_int(s0);
    }
}

// ================================================================
// K3: SpMM. out[n,i] = sum_{m in group(i)} values[m] * XT[j_m, n].
// 128 threads, 8 consecutive n per thread (16B gather/connection),
// ITILE=4, grid 4096. Packed entries staged in SMEM once per tile;
// gathers batched 8-wide (MLP=8).
// ================================================================
#define ITILE 4
#define NTHR  128
#define CHUNK 256

__device__ __forceinline__ void fma8(float acc[8], float v, uint4 u) {
    const __half2* h = (const __half2*)&u;
#pragma unroll
    for (int t = 0; t < 4; t++) {
        float2 f = __half22float2(h[t]);
        acc[2 * t]     += v * f.x;
        acc[2 * t + 1] += v * f.y;
    }
}

__global__ __launch_bounds__(NTHR) void k3_spmm(float* __restrict__ out) {
    __shared__ int2 se[CHUNK];
    __shared__ int  soff[ITILE + 1];

    int i0 = blockIdx.x * ITILE;
    int n0 = threadIdx.x * 8;

    if (threadIdx.x <= ITILE) soff[threadIdx.x] = g_rowstart[i0 + threadIdx.x];
    __syncthreads();

    int mbase = soff[0];
    int mend  = soff[ITILE];

    const char* xbase = (const char*)g_XTh + n0 * 2;

    float acc[ITILE][8];
#pragma unroll
    for (int k = 0; k < ITILE; k++)
#pragma unroll
        for (int r = 0; r < 8; r++) acc[k][r] = 0.f;

    for (int cb = mbase; cb < mend; cb += CHUNK) {
        int cend = min(cb + CHUNK, mend);
        __syncthreads();
        for (int t = threadIdx.x; cb + t < cend; t += NTHR)
            se[t] = g_packed[cb + t];
        __syncthreads();

#pragma unroll
        for (int il = 0; il < ITILE; il++) {
            int ms = max(soff[il], cb) - cb;
            int me = min(soff[il + 1], cend) - cb;
            int m = ms;
            for (; m + 8 <= me; m += 8) {
                int2 e0 = se[m],     e1 = se[m + 1], e2 = se[m + 2], e3 = se[m + 3];
                int2 e4 = se[m + 4], e5 = se[m + 5], e6 = se[m + 6], e7 = se[m + 7];
                uint4 u0 = *(const uint4*)(xbase + e0.x);
                uint4 u1 = *(const uint4*)(xbase + e1.x);
                uint4 u2 = *(const uint4*)(xbase + e2.x);
                uint4 u3 = *(const uint4*)(xbase + e3.x);
                uint4 u4 = *(const uint4*)(xbase + e4.x);
                uint4 u5 = *(const uint4*)(xbase + e5.x);
                uint4 u6 = *(const uint4*)(xbase + e6.x);
                uint4 u7 = *(const uint4*)(xbase + e7.x);
                fma8(acc[il], __int_as_float(e0.y), u0);
                fma8(acc[il], __int_as_float(e1.y), u1);
                fma8(acc[il], __int_as_float(e2.y), u2);
                fma8(acc[il], __int_as_float(e3.y), u3);
                fma8(acc[il], __int_as_float(e4.y), u4);
                fma8(acc[il], __int_as_float(e5.y), u5);
                fma8(acc[il], __int_as_float(e6.y), u6);
                fma8(acc[il], __int_as_float(e7.y), u7);
            }
            for (; m + 4 <= me; m += 4) {
                int2 e0 = se[m], e1 = se[m + 1], e2 = se[m + 2], e3 = se[m + 3];
                uint4 u0 = *(const uint4*)(xbase + e0.x);
                uint4 u1 = *(const uint4*)(xbase + e1.x);
                uint4 u2 = *(const uint4*)(xbase + e2.x);
                uint4 u3 = *(const uint4*)(xbase + e3.x);
                fma8(acc[il], __int_as_float(e0.y), u0);
                fma8(acc[il], __int_as_float(e1.y), u1);
                fma8(acc[il], __int_as_float(e2.y), u2);
                fma8(acc[il], __int_as_float(e3.y), u3);
            }
            for (; m < me; m++) {
                int2 e = se[m];
                uint4 u = *(const uint4*)(xbase + e.x);
                fma8(acc[il], __int_as_float(e.y), u);
            }
        }
    }

    // Write 4 contiguous i-outputs (one float4) per owned n row
#pragma unroll
    for (int r = 0; r < 8; r++) {
        *(float4*)(out + (size_t)(n0 + r) * FDIM + i0) =
            make_float4(acc[0][r], acc[1][r], acc[2][r], acc[3][r]);
    }
}

// ---------------------------------------------------------------
extern "C" void kernel_launch(void* const* d_in, const int* in_sizes, int n_in,
                              void* d_out, int out_size) {
    const float* up_facts = (const float*)d_in[0];   // [NB, F]
    const float* down_enc = (const float*)d_in[1];   // [F, D]
    const float* up_dec   = (const float*)d_in[2];   // [D, F]
    const void*  ii       = d_in[3];                 // [M] sorted (int32 or int64)
    const void*  jj       = d_in[4];                 // [M]
    float* out = (float*)d_out;                      // [NB, F]

    k1_prep<<<K1_TOT, 256>>>(up_dec, up_facts, ii, jj);
    k2_values<<<FDIM / 8, 256>>>(down_enc);
    k3_spmm<<<FDIM / ITILE, NTHR>>>(out);
}